// round 14
// baseline (speedup 1.0000x reference)
#include <cuda_runtime.h>
#include <cuda_fp16.h>
#include <cstdint>

// GeometricAttention via warp-level mma.sync m16n8k16 fp16 (f32 accumulate).
// Pre-pass converts K/V to fp16 rows in global scratch; V row gets an extra
// ones-dimension at d=144 so the PV MMA also produces the softmax row sum l
// (same f16 P as the numerator -> consistent). Q converted in-kernel (sign
// pattern, 1/12 scale, log2(e) folded). Softmax = cvt.rn.f16x2 + ex2.f16x2.
// 4 m-warps x 2 n-warps, raw row-major f16 smem (stride 76 u32, conflict-free
// ldmatrix), K/V double-buffered via cp.async. PV split: own-token half with
// register P (no barrier), partner half after a 64-thread pair barrier.

#define NTOK 2048
#define NBH  32
#define BQ   128
#define BK   64
#define NKT  (NTOK/BK)

#define RSTR 76            // row stride in u32 (152 halves)
// smem u32 offsets
#define QR_OFF 0           // [128][76]
#define KR_OFF 9728        // 2 x [64][76]
#define KR_SZ  4864
#define VR_OFF 19456       // 2 x [64][76]
#define VR_SZ  4864
#define PF_OFF 29184       // [mw4][nw2][mb2][kl2][lane32][4] = 4096
#define LR_OFF 33280       // [row128] floats
#define SM_U32 33536       // 134144 bytes

#define IPF_NEG 0xC0FCu    // dims (mod 16) with sign -1: 2..7, 14, 15
#define SCALE_Q 0.1202245867407469f   // log2(e)/12

// fp16 scratch: [bh][tok][152]
#define ROWH 152
__device__ __align__(16) static uint16_t g_kh[(size_t)NBH*NTOK*ROWH];
__device__ __align__(16) static uint16_t g_vh[(size_t)NBH*NTOK*ROWH];

__device__ __forceinline__ uint32_t pkh2(float lo, float hi){
    __half2 h = __floats2half2_rn(lo, hi);
    return *reinterpret_cast<uint32_t*>(&h);
}
// exp2 of a float pair -> f16x2 (lo, hi)
__device__ __forceinline__ uint32_t ex2h2(float lo, float hi){
    uint32_t r;
    asm("{ .reg .b32 t; cvt.rn.f16x2.f32 t, %1, %2; ex2.approx.f16x2 %0, t; }"
        : "=r"(r) : "f"(hi), "f"(lo));
    return r;
}
__device__ __forceinline__ uint32_t smem_u32(const void* p){
    uint32_t a;
    asm("{ .reg .u64 t; cvta.to.shared.u64 t, %1; cvt.u32.u64 %0, t; }"
        : "=r"(a) : "l"(p));
    return a;
}
__device__ __forceinline__ void cpa16(uint32_t dst, const void* src){
    asm volatile("cp.async.cg.shared.global [%0], [%1], 16;"
                 :: "r"(dst), "l"(src) : "memory");
}
#define CP_COMMIT() asm volatile("cp.async.commit_group;" ::: "memory")
#define CP_WAIT0()  asm volatile("cp.async.wait_group 0;" ::: "memory")

__device__ __forceinline__ void mma16(float* c, const uint32_t* a, const uint32_t* b){
    asm volatile("mma.sync.aligned.m16n8k16.row.col.f32.f16.f16.f32 "
        "{%0,%1,%2,%3}, {%4,%5,%6,%7}, {%8,%9}, {%0,%1,%2,%3};"
        : "+f"(c[0]), "+f"(c[1]), "+f"(c[2]), "+f"(c[3])
        : "r"(a[0]), "r"(a[1]), "r"(a[2]), "r"(a[3]), "r"(b[0]), "r"(b[1]));
}
__device__ __forceinline__ void ldsm_x4(uint32_t* r, uint32_t a){
    asm volatile("ldmatrix.sync.aligned.m8n8.x4.shared.b16 {%0,%1,%2,%3}, [%4];"
        : "=r"(r[0]), "=r"(r[1]), "=r"(r[2]), "=r"(r[3]) : "r"(a));
}
__device__ __forceinline__ void ldsm_x4t(uint32_t* r, uint32_t a){
    asm volatile("ldmatrix.sync.aligned.m8n8.x4.trans.shared.b16 {%0,%1,%2,%3}, [%4];"
        : "=r"(r[0]), "=r"(r[1]), "=r"(r[2]), "=r"(r[3]) : "r"(a));
}
__device__ __forceinline__ void ldsm_x2t(uint32_t* r, uint32_t a){
    asm volatile("ldmatrix.sync.aligned.m8n8.x2.trans.shared.b16 {%0,%1}, [%2];"
        : "=r"(r[0]), "=r"(r[1]) : "r"(a));
}

// ---------------- pre-pass: K/V fp32 -> fp16 rows (V gets ones col @144) -----
extern "C" __global__ void __launch_bounds__(256)
ga_prep_kernel(const float* __restrict__ k_mv, const float* __restrict__ v_mv,
               const float* __restrict__ k_s,  const float* __restrict__ v_s)
{
    const int idx = blockIdx.x * 256 + threadIdx.x;   // 65536*19 exact
    const int t = blockIdx.y;
    const int row = idx / 19, ch = idx % 19;
    uint16_t* dst = (t == 0 ? g_kh : g_vh) + (size_t)row*ROWH + ch*8;
    if (ch == 18){
        uint4 w = {0,0,0,0};
        if (t == 1) w.x = pkh2(1.0f, 0.0f);   // V dim 144 = 1.0 (row-sum column)
        *(uint4*)dst = w;
        return;
    }
    const float* mv = (t == 0 ? k_mv : v_mv);
    const float* sc = (t == 0 ? k_s  : v_s);
    float e[8];
    if (ch < 16){
        float4 a = *(const float4*)(mv + (size_t)row*128 + ch*8);
        float4 b = *(const float4*)(mv + (size_t)row*128 + ch*8 + 4);
        e[0]=a.x; e[1]=a.y; e[2]=a.z; e[3]=a.w;
        e[4]=b.x; e[5]=b.y; e[6]=b.z; e[7]=b.w;
    } else {
        float4 a = *(const float4*)(sc + (size_t)row*16 + (ch-16)*8);
        float4 b = *(const float4*)(sc + (size_t)row*16 + (ch-16)*8 + 4);
        e[0]=a.x; e[1]=a.y; e[2]=a.z; e[3]=a.w;
        e[4]=b.x; e[5]=b.y; e[6]=b.z; e[7]=b.w;
    }
    uint4 w;
    w.x = pkh2(e[0], e[1]);  w.y = pkh2(e[2], e[3]);
    w.z = pkh2(e[4], e[5]);  w.w = pkh2(e[6], e[7]);
    *(uint4*)dst = w;
}

// ---------------- main kernel ------------------------------------------------
extern "C" __global__ void __launch_bounds__(256, 1)
ga_cp_kernel(const float* __restrict__ q_mv, const float* __restrict__ q_s,
             float* __restrict__ out)
{
    extern __shared__ uint32_t smu[];
    float* smf = reinterpret_cast<float*>(smu);
    const uint32_t smb = smem_u32(smu);

    const int tid  = threadIdx.x;
    const int lane = tid & 31;
    const int w    = tid >> 5;
    const int mw   = w & 3;           // rows mw*32..+32
    const int nw   = w >> 2;          // S cols nw*32.. ; PV dims nw*72.. (+l col)
    const int bh   = blockIdx.y;
    const int qbase = blockIdx.x * BQ;

    const uint16_t* kbase = g_kh + (size_t)bh*NTOK*ROWH;
    const uint16_t* vbase = g_vh + (size_t)bh*NTOK*ROWH;

    // ---- stage K (18 chunks/row) + V (19 chunks/row incl. ones col) ----
    auto stage_kv = [&](int kb, int nb){
        const uint16_t* ks = kbase + (size_t)kb*ROWH;
        const uint16_t* vs = vbase + (size_t)kb*ROWH;
        #pragma unroll
        for (int i = 0; i < 10; i++){
            int idx = tid + 256*i;              // 0..2367
            if (idx < 2368){
                int tv = idx >= 1152;
                int r, ch;
                uint32_t dst;
                const uint16_t* src;
                if (!tv){
                    int li = idx;
                    r = li / 18;  ch = li % 18;
                    src = ks + r*ROWH + ch*8;
                    dst = smb + 4u*(KR_OFF + nb*KR_SZ + r*RSTR + ch*4);
                } else {
                    int li = idx - 1152;
                    r = li / 19;  ch = li % 19;
                    src = vs + r*ROWH + ch*8;
                    dst = smb + 4u*(VR_OFF + nb*VR_SZ + r*RSTR + ch*4);
                }
                cpa16(dst, src);
            }
        }
        CP_COMMIT();
    };

    // prologue: stage tile 0 (async) while converting Q rows in-kernel
    stage_kv(0, 0);
    {
        const int j = tid >> 1, h = tid & 1;
        const float* qmr = q_mv + ((size_t)bh*NTOK + qbase + j) * 128;
        const float* qsr = q_s  + ((size_t)bh*NTOK + qbase + j) * 16;
        #pragma unroll
        for (int i = 0; i < 18; i++){
            const int g = 18*h + i;                    // dims 4g..4g+3
            float4 v = (g < 32) ? *(const float4*)(qmr + 4*g)
                                : *(const float4*)(qsr + 4*(g-32));
            float e[4] = {v.x, v.y, v.z, v.w};
            #pragma unroll
            for (int ee = 0; ee < 4; ee++){
                const int d = 4*g + ee;
                float f = e[ee] * SCALE_Q;
                if (d < 128 && ((IPF_NEG >> (d & 15)) & 1)) f = -f;
                e[ee] = f;
            }
            uint2 wv; wv.x = pkh2(e[0], e[1]); wv.y = pkh2(e[2], e[3]);
            *(uint2*)&smu[QR_OFF + j*RSTR + 2*g] = wv;
        }
    }
    CP_WAIT0();
    __syncthreads();

    // ---- lane-dependent ldmatrix addresses (bytes) ----
    const int l = lane;
    uint32_t qA[2], kA[2], vA[5];
    #pragma unroll
    for (int mb = 0; mb < 2; mb++)
        qA[mb] = smb + 4u*(QR_OFF + (mw*32 + mb*16 + (l & 15))*RSTR + (l >> 4)*4);
    #pragma unroll
    for (int ntp = 0; ntp < 2; ntp++)
        kA[ntp] = smb + 4u*(KR_OFF + (nw*32 + ntp*16 + ((l >> 4) & 1)*8 + (l & 7))*RSTR
                            + ((l >> 3) & 1)*4);
    {
        const int tokv = ((l >> 3) & 1)*8 + (l & 7);
        #pragma unroll
        for (int p = 0; p < 5; p++)
            vA[p] = smb + 4u*(VR_OFF + tokv*RSTR + nw*36 + p*8 + (l >> 4)*4);
        if (nw == 0)
            vA[4] = smb + 4u*(VR_OFF + tokv*RSTR + 32);  // x2t: dims 64-71
    }

    // per-thread O accum: nw0 -> 9 n-tiles (dims 0-71); nw1 -> 10 (72-151, l@144)
    float o[2][10][4];
    #pragma unroll
    for (int a = 0; a < 2; a++)
        #pragma unroll
        for (int b = 0; b < 10; b++)
            #pragma unroll
            for (int z = 0; z < 4; z++) o[a][b][z] = 0.0f;

    // PV over one 32-token half for both mb row-blocks
    auto pv_half = [&](const uint4& A0, const uint4& A1, uint32_t vks){
        if (nw == 0){
            #pragma unroll
            for (int p = 0; p < 4; p++){
                uint32_t Bv[4];
                ldsm_x4t(Bv, vA[p] + vks);
                mma16(o[0][2*p],   (const uint32_t*)&A0, Bv);
                mma16(o[0][2*p+1], (const uint32_t*)&A0, Bv+2);
                mma16(o[1][2*p],   (const uint32_t*)&A1, Bv);
                mma16(o[1][2*p+1], (const uint32_t*)&A1, Bv+2);
            }
            uint32_t Bv2[2];
            ldsm_x2t(Bv2, vA[4] + vks);
            mma16(o[0][8], (const uint32_t*)&A0, Bv2);
            mma16(o[1][8], (const uint32_t*)&A1, Bv2);
        } else {
            #pragma unroll
            for (int p = 0; p < 5; p++){
                uint32_t Bv[4];
                ldsm_x4t(Bv, vA[p] + vks);
                mma16(o[0][2*p],   (const uint32_t*)&A0, Bv);
                mma16(o[0][2*p+1], (const uint32_t*)&A0, Bv+2);
                mma16(o[1][2*p],   (const uint32_t*)&A1, Bv);
                mma16(o[1][2*p+1], (const uint32_t*)&A1, Bv+2);
            }
        }
    };

    for (int kt = 0; kt < NKT; kt++){
        const int b = kt & 1;
        const uint32_t kbuf = (uint32_t)b * (KR_SZ * 4u);
        const uint32_t vbuf = (uint32_t)b * (VR_SZ * 4u);

        // ---------------- S = Q K^T (32 rows x 32 own cols per warp) --------
        float c[2][4][4];
        #pragma unroll
        for (int a = 0; a < 2; a++)
            #pragma unroll
            for (int n = 0; n < 4; n++)
                #pragma unroll
                for (int z = 0; z < 4; z++) c[a][n][z] = 0.0f;

        #pragma unroll
        for (int ks = 0; ks < 9; ks++){
            uint32_t A0[4], A1[4], B0[4], B1[4];
            ldsm_x4(A0, qA[0] + ks*32);
            ldsm_x4(A1, qA[1] + ks*32);
            ldsm_x4(B0, kA[0] + kbuf + ks*32);
            ldsm_x4(B1, kA[1] + kbuf + ks*32);
            mma16(c[0][0], A0, B0);     mma16(c[0][1], A0, B0+2);
            mma16(c[0][2], A0, B1);     mma16(c[0][3], A0, B1+2);
            mma16(c[1][0], A1, B0);     mma16(c[1][1], A1, B0+2);
            mma16(c[1][2], A1, B1);     mma16(c[1][3], A1, B1+2);
        }

        // ---------------- stage next tile (async, overlaps everything) ------
        if (kt + 1 < NKT) stage_kv((kt+1)*BK, b ^ 1);

        // ------- softmax: ex2.f16x2 -> P fragments directly ------------------
        uint4 pr[2][2];
        #pragma unroll
        for (int mb = 0; mb < 2; mb++){
            #pragma unroll
            for (int kl = 0; kl < 2; kl++){
                uint4 a;
                a.x = ex2h2(c[mb][2*kl][0],   c[mb][2*kl][1]);
                a.y = ex2h2(c[mb][2*kl][2],   c[mb][2*kl][3]);
                a.z = ex2h2(c[mb][2*kl+1][0], c[mb][2*kl+1][1]);
                a.w = ex2h2(c[mb][2*kl+1][2], c[mb][2*kl+1][3]);
                pr[mb][kl] = a;
                *(uint4*)&smu[PF_OFF + ((((mw*2+nw)*2+mb)*2+kl)*32 + lane)*4] = a;
            }
        }

        // -------- PV own-token half: P in registers, NO barrier needed -------
        #pragma unroll
        for (int kl = 0; kl < 2; kl++)
            pv_half(pr[0][kl], pr[1][kl],
                    vbuf + (uint32_t)(2*nw + kl) * (16*RSTR*4));

        // PF pair barrier: warps (mw,nw=0) and (mw,nw=1), 64 threads
        asm volatile("bar.sync %0, %1;" :: "r"(mw + 1), "r"(64) : "memory");

        // -------- PV partner-token half: P from PF ---------------------------
        #pragma unroll
        for (int kl = 0; kl < 2; kl++){
            const int owner = 1 - nw;
            uint4 A0 = *(const uint4*)&smu[PF_OFF + ((((mw*2+owner)*2+0)*2+kl)*32 + lane)*4];
            uint4 A1 = *(const uint4*)&smu[PF_OFF + ((((mw*2+owner)*2+1)*2+kl)*32 + lane)*4];
            pv_half(A0, A1, vbuf + (uint32_t)(2*owner + kl) * (16*RSTR*4));
        }

        CP_WAIT0();
        __syncthreads();   // staged tile visible; PF free for next iteration
    }

    // ---------------- l exchange: nw1 holds row sums at dim 144 --------------
    if (nw == 1 && (lane & 3) == 0){
        #pragma unroll
        for (int mb = 0; mb < 2; mb++){
            const int r = mw*32 + mb*16 + (lane >> 2);
            smf[LR_OFF + r]     = o[mb][9][0];
            smf[LR_OFF + r + 8] = o[mb][9][2];
        }
    }
    __syncthreads();

    // ---------------- epilogue -----------------------------------------------
    float* omv = out;
    float* osc = out + (size_t)NBH * NTOK * 128;
    #pragma unroll
    for (int mb = 0; mb < 2; mb++){
        const int r0 = mw*32 + mb*16 + (lane >> 2);
        const float inv0 = 1.0f / smf[LR_OFF + r0];
        const float inv1 = 1.0f / smf[LR_OFF + r0 + 8];
        const size_t g0 = (size_t)bh * NTOK + qbase + r0;
        #pragma unroll
        for (int nt = 0; nt < 9; nt++){
            const int col = nw*72 + nt*8 + 2*(lane & 3);
            float2 w0, w1;
            w0.x = o[mb][nt][0] * inv0;  w0.y = o[mb][nt][1] * inv0;
            w1.x = o[mb][nt][2] * inv1;  w1.y = o[mb][nt][3] * inv1;
            if (col < 128){
                *(float2*)(omv + g0*128 + col)     = w0;
                *(float2*)(omv + (g0+8)*128 + col) = w1;
            } else {
                *(float2*)(osc + g0*16 + (col-128))     = w0;
                *(float2*)(osc + (g0+8)*16 + (col-128)) = w1;
            }
        }
    }
}

extern "C" void kernel_launch(void* const* d_in, const int* in_sizes, int n_in,
                              void* d_out, int out_size)
{
    const float* q_mv = (const float*)d_in[0];
    const float* k_mv = (const float*)d_in[1];
    const float* v_mv = (const float*)d_in[2];
    const float* q_s  = (const float*)d_in[3];
    const float* k_s  = (const float*)d_in[4];
    const float* v_s  = (const float*)d_in[5];
    float* out = (float*)d_out;

    // pre-pass: K and V (65536 rows x 19 chunks each)
    ga_prep_kernel<<<dim3(4864, 2), 256>>>(k_mv, v_mv, k_s, v_s);

    cudaFuncSetAttribute(ga_cp_kernel, cudaFuncAttributeMaxDynamicSharedMemorySize,
                         SM_U32 * (int)sizeof(uint32_t));
    dim3 grid(NTOK / BQ, NBH);
    ga_cp_kernel<<<grid, 256, SM_U32 * sizeof(uint32_t)>>>(q_mv, q_s, out);
}

// round 16
// speedup vs baseline: 1.1093x; 1.1093x over previous
#include <cuda_runtime.h>
#include <cuda_fp16.h>
#include <cstdint>

// GeometricAttention via warp-level mma.sync m16n8k16 fp16 (f32 accumulate).
// Pre-pass converts K/V to fp16 rows in global scratch (18 chunks/row). The
// ones-column at d=144 (so PV MMA also produces softmax row sum l) is written
// once into both V smem buffers in the main-kernel prologue. Q converted
// in-kernel (sign pattern, 1/12 scale, log2(e) folded). Softmax = cvt.rn.f16x2
// + ex2.f16x2. 4 m-warps x 2 n-warps; raw row-major f16 smem (stride 76 u32,
// conflict-free ldmatrix); K/V double-buffered via cp.async with
// cp.async.mbarrier.arrive.NOINC (full[b], init 256) + empty[b] mbarriers --
// NO per-tile __syncthreads; warps slide to overlap tensor and L1 phases.
// PF double-buffered; SMSP co-resident warps mapped to different pair groups.

#define NTOK 2048
#define NBH  32
#define BQ   128
#define BK   64
#define NKT  (NTOK/BK)

#define RSTR 76            // row stride in u32 (152 halves)
// smem u32 offsets
#define QR_OFF 0           // [128][76]
#define KR_OFF 9728        // 2 x [64][76]
#define KR_SZ  4864
#define VR_OFF 19456       // 2 x [64][76]
#define VR_SZ  4864
#define PF_OFF 29184       // 2 x 4096 (double-buffered P exchange)
#define LR_OFF 37376       // [row128] floats
#define MB_OFF 37504       // 4 mbarriers (8B each), 8B-aligned
#define SM_U32 37512       // 150048 bytes

#define IPF_NEG 0xC0FCu    // dims (mod 16) with sign -1: 2..7, 14, 15
#define SCALE_Q 0.1202245867407469f   // log2(e)/12

// fp16 scratch: [bh][tok][152]
#define ROWH 152
__device__ __align__(16) static uint16_t g_kh[(size_t)NBH*NTOK*ROWH];
__device__ __align__(16) static uint16_t g_vh[(size_t)NBH*NTOK*ROWH];

__device__ __forceinline__ uint32_t pkh2(float lo, float hi){
    __half2 h = __floats2half2_rn(lo, hi);
    return *reinterpret_cast<uint32_t*>(&h);
}
// exp2 of a float pair -> f16x2 (lo, hi)
__device__ __forceinline__ uint32_t ex2h2(float lo, float hi){
    uint32_t r;
    asm("{ .reg .b32 t; cvt.rn.f16x2.f32 t, %1, %2; ex2.approx.f16x2 %0, t; }"
        : "=r"(r) : "f"(hi), "f"(lo));
    return r;
}
__device__ __forceinline__ uint32_t smem_u32(const void* p){
    uint32_t a;
    asm("{ .reg .u64 t; cvta.to.shared.u64 t, %1; cvt.u32.u64 %0, t; }"
        : "=r"(a) : "l"(p));
    return a;
}
__device__ __forceinline__ void cpa16(uint32_t dst, const void* src){
    asm volatile("cp.async.cg.shared.global [%0], [%1], 16;"
                 :: "r"(dst), "l"(src) : "memory");
}
#define MBAR_INIT(mb, c) asm volatile("mbarrier.init.shared.b64 [%0], %1;" :: "r"(mb), "r"(c) : "memory")
#define MBAR_ARRIVE(mb)  asm volatile("mbarrier.arrive.shared.b64 _, [%0];" :: "r"(mb) : "memory")
// NOINC: arrive-only (init pre-counts 256). The non-noinc form inc+dec's the
// pending count -- net zero against a pre-counted barrier -> phase never
// completes (the R15 hang).
#define CP_MBAR_ARRIVE(mb) asm volatile("cp.async.mbarrier.arrive.noinc.shared::cta.b64 [%0];" :: "r"(mb) : "memory")
#define MBAR_WAIT(mb, par) do {                                               \
    uint32_t _m = (mb), _p = (par), _d;                                       \
    asm volatile("{ .reg .pred p; mbarrier.try_wait.parity.acquire.cta.shared::cta.b64 p, [%1], %2; selp.b32 %0,1,0,p; }" \
        : "=r"(_d) : "r"(_m), "r"(_p) : "memory");                            \
    if (!_d) {                                                                \
        asm volatile("{ .reg .pred P1; WL_%=: mbarrier.try_wait.parity.acquire.cta.shared::cta.b64 P1, [%0], %1, 0x989680; @P1 bra.uni WD_%=; bra.uni WL_%=; WD_%=: }" \
            :: "r"(_m), "r"(_p) : "memory");                                  \
    }                                                                         \
} while(0)

__device__ __forceinline__ void mma16(float* c, const uint32_t* a, const uint32_t* b){
    asm volatile("mma.sync.aligned.m16n8k16.row.col.f32.f16.f16.f32 "
        "{%0,%1,%2,%3}, {%4,%5,%6,%7}, {%8,%9}, {%0,%1,%2,%3};"
        : "+f"(c[0]), "+f"(c[1]), "+f"(c[2]), "+f"(c[3])
        : "r"(a[0]), "r"(a[1]), "r"(a[2]), "r"(a[3]), "r"(b[0]), "r"(b[1]));
}
__device__ __forceinline__ void ldsm_x4(uint32_t* r, uint32_t a){
    asm volatile("ldmatrix.sync.aligned.m8n8.x4.shared.b16 {%0,%1,%2,%3}, [%4];"
        : "=r"(r[0]), "=r"(r[1]), "=r"(r[2]), "=r"(r[3]) : "r"(a));
}
__device__ __forceinline__ void ldsm_x4t(uint32_t* r, uint32_t a){
    asm volatile("ldmatrix.sync.aligned.m8n8.x4.trans.shared.b16 {%0,%1,%2,%3}, [%4];"
        : "=r"(r[0]), "=r"(r[1]), "=r"(r[2]), "=r"(r[3]) : "r"(a));
}
__device__ __forceinline__ void ldsm_x2t(uint32_t* r, uint32_t a){
    asm volatile("ldmatrix.sync.aligned.m8n8.x2.trans.shared.b16 {%0,%1}, [%2];"
        : "=r"(r[0]), "=r"(r[1]) : "r"(a));
}

// ---------------- pre-pass: K/V fp32 -> fp16 rows (18 chunks/row) ------------
extern "C" __global__ void __launch_bounds__(256)
ga_prep_kernel(const float* __restrict__ k_mv, const float* __restrict__ v_mv,
               const float* __restrict__ k_s,  const float* __restrict__ v_s)
{
    const int idx = blockIdx.x * 256 + threadIdx.x;   // 65536*18 exact
    const int t = blockIdx.y;
    const int row = idx / 18, ch = idx % 18;
    uint16_t* dst = (t == 0 ? g_kh : g_vh) + (size_t)row*ROWH + ch*8;
    const float* mv = (t == 0 ? k_mv : v_mv);
    const float* sc = (t == 0 ? k_s  : v_s);
    float e[8];
    if (ch < 16){
        float4 a = *(const float4*)(mv + (size_t)row*128 + ch*8);
        float4 b = *(const float4*)(mv + (size_t)row*128 + ch*8 + 4);
        e[0]=a.x; e[1]=a.y; e[2]=a.z; e[3]=a.w;
        e[4]=b.x; e[5]=b.y; e[6]=b.z; e[7]=b.w;
    } else {
        float4 a = *(const float4*)(sc + (size_t)row*16 + (ch-16)*8);
        float4 b = *(const float4*)(sc + (size_t)row*16 + (ch-16)*8 + 4);
        e[0]=a.x; e[1]=a.y; e[2]=a.z; e[3]=a.w;
        e[4]=b.x; e[5]=b.y; e[6]=b.z; e[7]=b.w;
    }
    uint4 w;
    w.x = pkh2(e[0], e[1]);  w.y = pkh2(e[2], e[3]);
    w.z = pkh2(e[4], e[5]);  w.w = pkh2(e[6], e[7]);
    *(uint4*)dst = w;
}

// ---------------- main kernel ------------------------------------------------
extern "C" __global__ void __launch_bounds__(256, 1)
ga_cp_kernel(const float* __restrict__ q_mv, const float* __restrict__ q_s,
             float* __restrict__ out)
{
    extern __shared__ uint32_t smu[];
    float* smf = reinterpret_cast<float*>(smu);
    const uint32_t smb = smem_u32(smu);

    const int tid  = threadIdx.x;
    const int lane = tid & 31;
    const int w    = tid >> 5;
    const int nw   = w >> 2;          // S cols nw*32.. ; PV dims nw*72.. (+l col)
    // pair-group remap: SMSP co-residents (w, w+4) land in DIFFERENT pairs
    const int mw   = nw ? (((w & 3) + 1) & 3) : (w & 3);   // rows mw*32..+32
    const int bh   = blockIdx.y;
    const int qbase = blockIdx.x * BQ;

    const uint32_t mbF0 = smb + 4u*MB_OFF;
    const uint32_t mbF1 = mbF0 + 8, mbE0 = mbF0 + 16, mbE1 = mbF0 + 24;

    const uint16_t* kbase = g_kh + (size_t)bh*NTOK*ROWH;
    const uint16_t* vbase = g_vh + (size_t)bh*NTOK*ROWH;

    // ---- stage K + V (18 chunks/row each, 2304 = 9/thread exact) ----
    auto stage_kv = [&](int kb, int nb, uint32_t mbF){
        const uint16_t* ks = kbase + (size_t)kb*ROWH;
        const uint16_t* vs = vbase + (size_t)kb*ROWH;
        #pragma unroll
        for (int i = 0; i < 9; i++){
            int idx = tid + 256*i;              // 0..2303
            int tv = idx >= 1152;
            int li = idx - tv*1152;
            int r = li / 18, ch = li % 18;
            const uint16_t* src = (tv ? vs : ks) + r*ROWH + ch*8;
            uint32_t dst = smb + 4u*((tv ? VR_OFF + nb*VR_SZ
                                         : KR_OFF + nb*KR_SZ) + r*RSTR + ch*4);
            cpa16(dst, src);
        }
        CP_MBAR_ARRIVE(mbF);
    };

    // prologue: init mbarriers, ones-column into both V buffers, stage tile 0,
    // convert Q rows in-kernel
    if (tid == 0){
        MBAR_INIT(mbF0, 256); MBAR_INIT(mbF1, 256);
        MBAR_INIT(mbE0, 256); MBAR_INIT(mbE1, 256);
    }
    if (tid < 128){
        const int nb = tid >> 6, r = tid & 63;
        uint4 ones; ones.x = pkh2(1.0f, 0.0f); ones.y = 0; ones.z = 0; ones.w = 0;
        *(uint4*)&smu[VR_OFF + nb*VR_SZ + r*RSTR + 72] = ones;  // dims 144-151
    }
    __syncthreads();
    stage_kv(0, 0, mbF0);
    {
        const int j = tid >> 1, h = tid & 1;
        const float* qmr = q_mv + ((size_t)bh*NTOK + qbase + j) * 128;
        const float* qsr = q_s  + ((size_t)bh*NTOK + qbase + j) * 16;
        #pragma unroll
        for (int i = 0; i < 18; i++){
            const int g = 18*h + i;                    // dims 4g..4g+3
            float4 v = (g < 32) ? *(const float4*)(qmr + 4*g)
                                : *(const float4*)(qsr + 4*(g-32));
            float e[4] = {v.x, v.y, v.z, v.w};
            #pragma unroll
            for (int ee = 0; ee < 4; ee++){
                const int d = 4*g + ee;
                float f = e[ee] * SCALE_Q;
                if (d < 128 && ((IPF_NEG >> (d & 15)) & 1)) f = -f;
                e[ee] = f;
            }
            uint2 wv; wv.x = pkh2(e[0], e[1]); wv.y = pkh2(e[2], e[3]);
            *(uint2*)&smu[QR_OFF + j*RSTR + 2*g] = wv;
        }
    }
    __syncthreads();     // Q + ones + mbarriers visible to all warps

    // ---- lane-dependent ldmatrix addresses (bytes) ----
    const int l = lane;
    uint32_t qA[2], kA[2], vA[5];
    #pragma unroll
    for (int mb = 0; mb < 2; mb++)
        qA[mb] = smb + 4u*(QR_OFF + (mw*32 + mb*16 + (l & 15))*RSTR + (l >> 4)*4);
    #pragma unroll
    for (int ntp = 0; ntp < 2; ntp++)
        kA[ntp] = smb + 4u*(KR_OFF + (nw*32 + ntp*16 + ((l >> 4) & 1)*8 + (l & 7))*RSTR
                            + ((l >> 3) & 1)*4);
    {
        const int tokv = ((l >> 3) & 1)*8 + (l & 7);
        #pragma unroll
        for (int p = 0; p < 5; p++)
            vA[p] = smb + 4u*(VR_OFF + tokv*RSTR + nw*36 + p*8 + (l >> 4)*4);
        if (nw == 0)
            vA[4] = smb + 4u*(VR_OFF + tokv*RSTR + 32);  // x2t: dims 64-71
    }

    // per-thread O accum: nw0 -> 9 n-tiles (dims 0-71); nw1 -> 10 (72-151, l@144)
    float o[2][10][4];
    #pragma unroll
    for (int a = 0; a < 2; a++)
        #pragma unroll
        for (int b = 0; b < 10; b++)
            #pragma unroll
            for (int z = 0; z < 4; z++) o[a][b][z] = 0.0f;

    auto pv_half = [&](const uint4& A0, const uint4& A1, uint32_t vks){
        if (nw == 0){
            #pragma unroll
            for (int p = 0; p < 4; p++){
                uint32_t Bv[4];
                ldsm_x4t(Bv, vA[p] + vks);
                mma16(o[0][2*p],   (const uint32_t*)&A0, Bv);
                mma16(o[0][2*p+1], (const uint32_t*)&A0, Bv+2);
                mma16(o[1][2*p],   (const uint32_t*)&A1, Bv);
                mma16(o[1][2*p+1], (const uint32_t*)&A1, Bv+2);
            }
            uint32_t Bv2[2];
            ldsm_x2t(Bv2, vA[4] + vks);
            mma16(o[0][8], (const uint32_t*)&A0, Bv2);
            mma16(o[1][8], (const uint32_t*)&A1, Bv2);
        } else {
            #pragma unroll
            for (int p = 0; p < 5; p++){
                uint32_t Bv[4];
                ldsm_x4t(Bv, vA[p] + vks);
                mma16(o[0][2*p],   (const uint32_t*)&A0, Bv);
                mma16(o[0][2*p+1], (const uint32_t*)&A0, Bv+2);
                mma16(o[1][2*p],   (const uint32_t*)&A1, Bv);
                mma16(o[1][2*p+1], (const uint32_t*)&A1, Bv+2);
            }
        }
    };

    for (int kt = 0; kt < NKT; kt++){
        const int b = kt & 1;
        const uint32_t kbuf = (uint32_t)b * (KR_SZ * 4u);
        const uint32_t vbuf = (uint32_t)b * (VR_SZ * 4u);

        // K/V(kt) staged (cp.async complete across all 256 threads)?
        MBAR_WAIT(b ? mbF1 : mbF0, (kt >> 1) & 1);

        // ---------------- S = Q K^T (32 rows x 32 own cols per warp) --------
        float c[2][4][4];
        #pragma unroll
        for (int a = 0; a < 2; a++)
            #pragma unroll
            for (int n = 0; n < 4; n++)
                #pragma unroll
                for (int z = 0; z < 4; z++) c[a][n][z] = 0.0f;

        #pragma unroll
        for (int ks = 0; ks < 9; ks++){
            uint32_t A0[4], A1[4], B0[4], B1[4];
            ldsm_x4(A0, qA[0] + ks*32);
            ldsm_x4(A1, qA[1] + ks*32);
            ldsm_x4(B0, kA[0] + kbuf + ks*32);
            ldsm_x4(B1, kA[1] + kbuf + ks*32);
            mma16(c[0][0], A0, B0);     mma16(c[0][1], A0, B0+2);
            mma16(c[0][2], A0, B1);     mma16(c[0][3], A0, B1+2);
            mma16(c[1][0], A1, B0);     mma16(c[1][1], A1, B0+2);
            mma16(c[1][2], A1, B1);     mma16(c[1][3], A1, B1+2);
        }

        // ------- stage tile kt+1 into alternate buffer (guarded by empty) ----
        if (kt + 1 < NKT){
            const int sb = (kt + 1) & 1;
            if (kt >= 1) MBAR_WAIT(sb ? mbE1 : mbE0, ((kt - 1) >> 1) & 1);
            stage_kv((kt + 1) * BK, sb, sb ? mbF1 : mbF0);
        }

        // ------- softmax: ex2.f16x2 -> P fragments; PF double-buffered -------
        const uint32_t pf = PF_OFF + (uint32_t)(kt & 1) * 4096u;
        uint4 pr[2][2];
        #pragma unroll
        for (int mb = 0; mb < 2; mb++){
            #pragma unroll
            for (int kl = 0; kl < 2; kl++){
                uint4 a;
                a.x = ex2h2(c[mb][2*kl][0],   c[mb][2*kl][1]);
                a.y = ex2h2(c[mb][2*kl][2],   c[mb][2*kl][3]);
                a.z = ex2h2(c[mb][2*kl+1][0], c[mb][2*kl+1][1]);
                a.w = ex2h2(c[mb][2*kl+1][2], c[mb][2*kl+1][3]);
                pr[mb][kl] = a;
                *(uint4*)&smu[pf + ((((mw*2+nw)*2+mb)*2+kl)*32 + lane)*4] = a;
            }
        }

        // -------- PV own-token half: P in registers, NO barrier needed -------
        #pragma unroll
        for (int kl = 0; kl < 2; kl++)
            pv_half(pr[0][kl], pr[1][kl],
                    vbuf + (uint32_t)(2*nw + kl) * (16*RSTR*4));

        // PF pair barrier: the two warps sharing pair id mw (64 threads)
        asm volatile("bar.sync %0, %1;" :: "r"(mw + 1), "r"(64) : "memory");

        // -------- PV partner-token half: P from PF ---------------------------
        #pragma unroll
        for (int kl = 0; kl < 2; kl++){
            const int owner = 1 - nw;
            uint4 A0 = *(const uint4*)&smu[pf + ((((mw*2+owner)*2+0)*2+kl)*32 + lane)*4];
            uint4 A1 = *(const uint4*)&smu[pf + ((((mw*2+owner)*2+1)*2+kl)*32 + lane)*4];
            pv_half(A0, A1, vbuf + (uint32_t)(2*owner + kl) * (16*RSTR*4));
        }

        // done reading K/V buffer b for this tile
        MBAR_ARRIVE(b ? mbE1 : mbE0);
    }

    // ---------------- l exchange: nw1 holds row sums at dim 144 --------------
    __syncthreads();
    if (nw == 1 && (lane & 3) == 0){
        #pragma unroll
        for (int mb = 0; mb < 2; mb++){
            const int r = mw*32 + mb*16 + (lane >> 2);
            smf[LR_OFF + r]     = o[mb][9][0];
            smf[LR_OFF + r + 8] = o[mb][9][2];
        }
    }
    __syncthreads();

    // ---------------- epilogue -----------------------------------------------
    float* omv = out;
    float* osc = out + (size_t)NBH * NTOK * 128;
    #pragma unroll
    for (int mb = 0; mb < 2; mb++){
        const int r0 = mw*32 + mb*16 + (lane >> 2);
        const float inv0 = 1.0f / smf[LR_OFF + r0];
        const float inv1 = 1.0f / smf[LR_OFF + r0 + 8];
        const size_t g0 = (size_t)bh * NTOK + qbase + r0;
        #pragma unroll
        for (int nt = 0; nt < 9; nt++){
            const int col = nw*72 + nt*8 + 2*(lane & 3);
            float2 w0, w1;
            w0.x = o[mb][nt][0] * inv0;  w0.y = o[mb][nt][1] * inv0;
            w1.x = o[mb][nt][2] * inv1;  w1.y = o[mb][nt][3] * inv1;
            if (col < 128){
                *(float2*)(omv + g0*128 + col)     = w0;
                *(float2*)(omv + (g0+8)*128 + col) = w1;
            } else {
                *(float2*)(osc + g0*16 + (col-128))     = w0;
                *(float2*)(osc + (g0+8)*16 + (col-128)) = w1;
            }
        }
    }
}

extern "C" void kernel_launch(void* const* d_in, const int* in_sizes, int n_in,
                              void* d_out, int out_size)
{
    const float* q_mv = (const float*)d_in[0];
    const float* k_mv = (const float*)d_in[1];
    const float* v_mv = (const float*)d_in[2];
    const float* q_s  = (const float*)d_in[3];
    const float* k_s  = (const float*)d_in[4];
    const float* v_s  = (const float*)d_in[5];
    float* out = (float*)d_out;

    // pre-pass: K and V (65536 rows x 18 chunks each)
    ga_prep_kernel<<<dim3(4608, 2), 256>>>(k_mv, v_mv, k_s, v_s);

    cudaFuncSetAttribute(ga_cp_kernel, cudaFuncAttributeMaxDynamicSharedMemorySize,
                         SM_U32 * (int)sizeof(uint32_t));
    dim3 grid(NTOK / BQ, NBH);
    ga_cp_kernel<<<grid, 256, SM_U32 * sizeof(uint32_t)>>>(q_mv, q_s, out);
}